// round 15
// baseline (speedup 1.0000x reference)
#include <cuda_runtime.h>
#include <cuda_fp16.h>
#include <math.h>
#include <stdint.h>

// ---------------- problem constants ----------------
#define NB    4096
#define NDG   1024
#define NDI   1024
#define NHG   512
#define NE    8
#define NH    2048
#define NC    512
#define TEMPR 5.0f
#define NASSIGN (NB*2)

// ---------------- scratch ----------------
__device__ float  g_hg[NB * NHG];
__device__ float  g_gates[NB * NE];
__device__ int    g_cnt[NE];
__device__ int    g_off[NE];
__device__ int    g_rowlist[NE * NB];
__device__ float  g_gatelist[NE * NB];
__device__ int    g_rowexp[NB * 2];
__device__ int    g_rowpos[NB * 2];
__device__ __half g_He[(size_t)NASSIGN * NH];
__device__ float  g_P[(size_t)NASSIGN * NC];
__device__ float  g_loss;

__global__ void zero_counts() {
    if (threadIdx.x < NE) g_cnt[threadIdx.x] = 0;
}
__global__ void offsets_kernel() {
    if (threadIdx.x == 0) {
        int o = 0;
        for (int e = 0; e < NE; e++) { g_off[e] = o; o += g_cnt[e]; }
    }
}

// ---------------- helpers ----------------
__device__ __forceinline__ uint32_t smem_u32(const void* p) {
    uint32_t a;
    asm("{ .reg .u64 t; cvta.to.shared.u64 t, %1; cvt.u32.u64 %0, t; }" : "=r"(a) : "l"(p));
    return a;
}
__device__ __forceinline__ uint32_t packh(float a, float b) {
    __half2 h = __floats2half2_rn(a, b);
    return *reinterpret_cast<uint32_t*>(&h);
}
__device__ __forceinline__ void mma_fp16(float* d, const uint32_t* a,
                                         const uint32_t* b, const float* c) {
    asm volatile(
        "mma.sync.aligned.m16n8k16.row.col.f32.f16.f16.f32 "
        "{%0,%1,%2,%3}, {%4,%5,%6,%7}, {%8,%9}, {%10,%11,%12,%13};\n"
        : "=f"(d[0]), "=f"(d[1]), "=f"(d[2]), "=f"(d[3])
        : "r"(a[0]), "r"(a[1]), "r"(a[2]), "r"(a[3]),
          "r"(b[0]), "r"(b[1]),
          "f"(c[0]), "f"(c[1]), "f"(c[2]), "f"(c[3]));
}
__device__ __forceinline__ void ldsm_x4(uint32_t* d, uint32_t saddr) {
    asm volatile("ldmatrix.sync.aligned.m8n8.x4.shared.b16 {%0,%1,%2,%3}, [%4];"
        : "=r"(d[0]), "=r"(d[1]), "=r"(d[2]), "=r"(d[3]) : "r"(saddr));
}

// ============================================================================
// Expert GEMMs — EXACT R8/R14 source (proven local optimum).
// MODE 1: He = relu(gather(x2) @ W1[e] + b1[e])   M=cnt_e N=2048 K=1024
// MODE 2: P  = He @ W2[e] + b2[e]                 M=cnt_e N=512  K=2048
// ============================================================================
template<int MODE>
__global__ __launch_bounds__(256, 2)
void emma(const float* __restrict__ Af,
          const float* __restrict__ Wall,
          const float* __restrict__ biasAll)
{
    constexpr int BM = 128, BK = 32;
    constexpr int LDA = 20, LDB = 136;

    const int e = blockIdx.z;
    const int M = g_cnt[e];
    const int m0 = blockIdx.y * BM;
    if (m0 >= M) return;
    const int n0 = blockIdx.x * 128;

    constexpr int Kd  = (MODE == 1) ? NDI : NH;
    constexpr int ldw = (MODE == 1) ? NH  : NC;
    const float* W    = Wall + (size_t)e * Kd * ldw;
    const float* bias = biasAll + e * ldw;
    const int* rowlist = g_rowlist + e * NB;
    const size_t offE = (size_t)g_off[e];
    const __half* Ab = g_He + offE * NH;

    __shared__ uint32_t As[2][BM][LDA];
    __shared__ uint32_t Bs[2][16][LDB];

    const int tid = threadIdx.x;
    int arow[2], akc[2];
    size_t aoff[2];
#pragma unroll
    for (int c = 0; c < 2; c++) {
        int q = tid + 256 * c;
        arow[c] = q >> 2;
        akc[c]  = (q & 3) * 8;
        int gm = m0 + arow[c];
        if (MODE == 1) {
            int r = (gm < M) ? rowlist[gm] : rowlist[0];
            aoff[c] = (size_t)r * NDI;
        } else {
            int r = (gm < M) ? gm : 0;
            aoff[c] = (size_t)r * NH;
        }
    }
    int bkp[2], bnq[2];
#pragma unroll
    for (int c = 0; c < 2; c++) {
        int q = tid + 256 * c;
        bkp[c] = q >> 5;
        bnq[c] = (q & 31) * 4;
    }

    const int warp = tid >> 5;
    const int wm = warp >> 1, wn = warp & 1;
    const int lane = tid & 31;
    const int g = lane >> 2, tg = lane & 3;

    const uint32_t asbase = smem_u32(&As[0][0][0]);
    const int lr = lane & 15;
    const int lc = (lane >> 2) & 4;

    float acc[2][8][4];
#pragma unroll
    for (int i = 0; i < 2; i++)
#pragma unroll
        for (int j = 0; j < 8; j++)
#pragma unroll
            for (int q = 0; q < 4; q++) acc[i][j][q] = 0.0f;

    float4 ra[2][2];
    uint4  rab[2];
    float4 rb[2][2];

    auto LDGt = [&](int k0) {
#pragma unroll
        for (int c = 0; c < 2; c++) {
            if (MODE == 1) {
                ra[c][0] = *(const float4*)(Af + aoff[c] + k0 + akc[c]);
                ra[c][1] = *(const float4*)(Af + aoff[c] + k0 + akc[c] + 4);
            } else {
                rab[c] = *(const uint4*)(Ab + aoff[c] + k0 + akc[c]);
            }
        }
#pragma unroll
        for (int c = 0; c < 2; c++) {
            rb[c][0] = *(const float4*)(W + (size_t)(k0 + 2 * bkp[c]) * ldw + n0 + bnq[c]);
            rb[c][1] = *(const float4*)(W + (size_t)(k0 + 2 * bkp[c] + 1) * ldw + n0 + bnq[c]);
        }
    };
    auto STSt = [&](int s) {
#pragma unroll
        for (int c = 0; c < 2; c++) {
            if (MODE == 1) {
                uint4 u;
                u.x = packh(ra[c][0].x, ra[c][0].y);
                u.y = packh(ra[c][0].z, ra[c][0].w);
                u.z = packh(ra[c][1].x, ra[c][1].y);
                u.w = packh(ra[c][1].z, ra[c][1].w);
                *(uint4*)&As[s][arow[c]][akc[c] >> 1] = u;
            } else {
                *(uint4*)&As[s][arow[c]][akc[c] >> 1] = rab[c];
            }
        }
#pragma unroll
        for (int c = 0; c < 2; c++) {
            uint4 u;
            u.x = packh(rb[c][0].x, rb[c][1].x);
            u.y = packh(rb[c][0].y, rb[c][1].y);
            u.z = packh(rb[c][0].z, rb[c][1].z);
            u.w = packh(rb[c][0].w, rb[c][1].w);
            *(uint4*)&Bs[s][bkp[c]][bnq[c]] = u;
        }
    };

    LDGt(0);
    STSt(0);
    __syncthreads();

    const int T = Kd / BK;
    for (int t = 0; t < T; t++) {
        const int s = t & 1;
        if (t + 1 < T) LDGt((t + 1) * BK);

#pragma unroll
        for (int ksub = 0; ksub < 2; ksub++) {
            const int kb = ksub * 8;
            uint32_t af[2][4];
#pragma unroll
            for (int mt = 0; mt < 2; mt++) {
                const int mr = wm * 32 + mt * 16;
                const uint32_t addr = asbase +
                    ((uint32_t)(s * BM * LDA + (mr + lr) * LDA + kb + lc)) * 4u;
                ldsm_x4(af[mt], addr);
            }
#pragma unroll
            for (int nt = 0; nt < 8; nt++) {
                const int nc = wn * 64 + nt * 8 + g;
                uint32_t bf[2];
                bf[0] = Bs[s][kb + tg    ][nc];
                bf[1] = Bs[s][kb + tg + 4][nc];
#pragma unroll
                for (int mt = 0; mt < 2; mt++)
                    mma_fp16(acc[mt][nt], af[mt], bf, acc[mt][nt]);
            }
        }

        if (t + 1 < T) {
            STSt((t + 1) & 1);
            __syncthreads();
        }
    }

    __half* Ch = g_He + offE * NH;
    float*  Cf = g_P  + offE * NC;
#pragma unroll
    for (int mt = 0; mt < 2; mt++) {
        const int gm1 = m0 + wm * 32 + mt * 16 + g;
        const int gm2 = gm1 + 8;
#pragma unroll
        for (int nt = 0; nt < 8; nt++) {
            const int col = n0 + wn * 64 + nt * 8 + tg * 2;
            const float b0 = bias[col], b1 = bias[col + 1];
            if (MODE == 1) {
                if (gm1 < M) {
                    float v0 = fmaxf(acc[mt][nt][0] + b0, 0.f);
                    float v1 = fmaxf(acc[mt][nt][1] + b1, 0.f);
                    *(uint32_t*)(Ch + (size_t)gm1 * NH + col) = packh(v0, v1);
                }
                if (gm2 < M) {
                    float v0 = fmaxf(acc[mt][nt][2] + b0, 0.f);
                    float v1 = fmaxf(acc[mt][nt][3] + b1, 0.f);
                    *(uint32_t*)(Ch + (size_t)gm2 * NH + col) = packh(v0, v1);
                }
            } else {
                if (gm1 < M)
                    *(float2*)(Cf + (size_t)gm1 * NC + col) =
                        make_float2(acc[mt][nt][0] + b0, acc[mt][nt][1] + b1);
                if (gm2 < M)
                    *(float2*)(Cf + (size_t)gm2 * NC + col) =
                        make_float2(acc[mt][nt][2] + b0, acc[mt][nt][3] + b1);
            }
        }
    }
}

// ============================================================================
// Gating layer 1: fp16-split, arithmetic frozen; R14 register prefetch +
// NEW: ldmatrix fragment loads (values bitwise identical to scalar LDS).
// ============================================================================
__global__ __launch_bounds__(256, 2)
void gemm0_split(const float* __restrict__ A,
                 const float* __restrict__ W,
                 const float* __restrict__ bias)
{
    constexpr int BM = 128, BK = 32;
    constexpr int LDA = 20, LDB = 136;
    constexpr int ldw = NHG;

    const int m0 = blockIdx.y * BM;
    const int n0 = blockIdx.x * 128;

    __shared__ uint32_t AsH[BM][LDA];
    __shared__ uint32_t AsL[BM][LDA];
    __shared__ uint32_t BsH[16][LDB];
    __shared__ uint32_t BsL[16][LDB];

    const int tid = threadIdx.x;
    int arow[2], akc[2];
    size_t aoff[2];
#pragma unroll
    for (int c = 0; c < 2; c++) {
        int q = tid + 256 * c;
        arow[c] = q >> 2;
        akc[c]  = (q & 3) * 8;
        aoff[c] = (size_t)(m0 + arow[c]) * NDG;
    }
    int bkp[2], bnq[2];
#pragma unroll
    for (int c = 0; c < 2; c++) {
        int q = tid + 256 * c;
        bkp[c] = q >> 5;
        bnq[c] = (q & 31) * 4;
    }

    const int warp = tid >> 5;
    const int wm = warp >> 1, wn = warp & 1;
    const int lane = tid & 31;
    const int g = lane >> 2, tg = lane & 3;

    const uint32_t asHbase = smem_u32(&AsH[0][0]);
    const uint32_t asLbase = smem_u32(&AsL[0][0]);
    const int lr = lane & 15;
    const int lc = (lane >> 2) & 4;

    float acc[2][8][4];
#pragma unroll
    for (int i = 0; i < 2; i++)
#pragma unroll
        for (int j = 0; j < 8; j++)
#pragma unroll
            for (int q = 0; q < 4; q++) acc[i][j][q] = 0.0f;

    auto splitpack = [](float a, float b, uint32_t& uh, uint32_t& ul) {
        __half ha = __float2half_rn(a);
        __half hb = __float2half_rn(b);
        float la = a - __half2float(ha);
        float lb = b - __half2float(hb);
        __half2 h2; h2.x = ha; h2.y = hb;
        uh = *reinterpret_cast<uint32_t*>(&h2);
        ul = packh(la, lb);
    };

    float4 ra[2][2], rb[2][2];   // persistent register staging (tile t)

    auto LDGt = [&](int k0) {
#pragma unroll
        for (int c = 0; c < 2; c++) {
            ra[c][0] = *(const float4*)(A + aoff[c] + k0 + akc[c]);
            ra[c][1] = *(const float4*)(A + aoff[c] + k0 + akc[c] + 4);
            rb[c][0] = *(const float4*)(W + (size_t)(k0 + 2 * bkp[c]) * ldw + n0 + bnq[c]);
            rb[c][1] = *(const float4*)(W + (size_t)(k0 + 2 * bkp[c] + 1) * ldw + n0 + bnq[c]);
        }
    };
    auto STSt = [&]() {
#pragma unroll
        for (int c = 0; c < 2; c++) {
            uint4 uh, ul;
            splitpack(ra[c][0].x, ra[c][0].y, uh.x, ul.x);
            splitpack(ra[c][0].z, ra[c][0].w, uh.y, ul.y);
            splitpack(ra[c][1].x, ra[c][1].y, uh.z, ul.z);
            splitpack(ra[c][1].z, ra[c][1].w, uh.w, ul.w);
            *(uint4*)&AsH[arow[c]][akc[c] >> 1] = uh;
            *(uint4*)&AsL[arow[c]][akc[c] >> 1] = ul;
        }
#pragma unroll
        for (int c = 0; c < 2; c++) {
            uint4 uh, ul;
            splitpack(rb[c][0].x, rb[c][1].x, uh.x, ul.x);
            splitpack(rb[c][0].y, rb[c][1].y, uh.y, ul.y);
            splitpack(rb[c][0].z, rb[c][1].z, uh.z, ul.z);
            splitpack(rb[c][0].w, rb[c][1].w, uh.w, ul.w);
            *(uint4*)&BsH[bkp[c]][bnq[c]] = uh;
            *(uint4*)&BsL[bkp[c]][bnq[c]] = ul;
        }
    };

    const int T = NDG / BK;
    LDGt(0);
    for (int t = 0; t < T; t++) {
        __syncthreads();
        STSt();
        __syncthreads();
        if (t + 1 < T) LDGt((t + 1) * BK);   // prefetch overlaps mma below

#pragma unroll
        for (int ksub = 0; ksub < 2; ksub++) {
            const int kb = ksub * 8;
            uint32_t afh[2][4], afl[2][4];
#pragma unroll
            for (int mt = 0; mt < 2; mt++) {
                const int mr = wm * 32 + mt * 16;
                const uint32_t off = ((uint32_t)((mr + lr) * LDA + kb + lc)) * 4u;
                ldsm_x4(afh[mt], asHbase + off);
                ldsm_x4(afl[mt], asLbase + off);
            }
#pragma unroll
            for (int nt = 0; nt < 8; nt++) {
                const int nc = wn * 64 + nt * 8 + g;
                uint32_t bfh[2], bfl[2];
                bfh[0] = BsH[kb + tg    ][nc];
                bfh[1] = BsH[kb + tg + 4][nc];
                bfl[0] = BsL[kb + tg    ][nc];
                bfl[1] = BsL[kb + tg + 4][nc];
#pragma unroll
                for (int mt = 0; mt < 2; mt++) {
                    mma_fp16(acc[mt][nt], afh[mt], bfh, acc[mt][nt]);
                    mma_fp16(acc[mt][nt], afh[mt], bfl, acc[mt][nt]);
                    mma_fp16(acc[mt][nt], afl[mt], bfh, acc[mt][nt]);
                }
            }
        }
    }

#pragma unroll
    for (int mt = 0; mt < 2; mt++) {
        const int gm1 = m0 + wm * 32 + mt * 16 + g;
        const int gm2 = gm1 + 8;
#pragma unroll
        for (int nt = 0; nt < 8; nt++) {
            const int col = n0 + wn * 64 + nt * 8 + tg * 2;
            const float b0 = bias[col], b1 = bias[col + 1];
            *(float2*)(g_hg + (size_t)gm1 * NHG + col) =
                make_float2(fmaxf(acc[mt][nt][0] + b0, 0.f), fmaxf(acc[mt][nt][1] + b1, 0.f));
            *(float2*)(g_hg + (size_t)gm2 * NHG + col) =
                make_float2(fmaxf(acc[mt][nt][2] + b0, 0.f), fmaxf(acc[mt][nt][3] + b1, 0.f));
        }
    }
}

// ---------------- gating layer 2 + top-2 + dispatch (FROZEN) ----------------
__global__ __launch_bounds__(256)
void gating_topk(const float* __restrict__ Wg2, const float* __restrict__ bg2)
{
    __shared__ float sW[NE][NHG];
    __shared__ float sb[NE];
    const int tid = threadIdx.x;
    for (int i = tid; i < NE * NHG; i += 256)
        sW[i >> 9][i & (NHG - 1)] = Wg2[(i & (NHG - 1)) * NE + (i >> 9)];
    if (tid < NE) sb[tid] = bg2[tid];
    __syncthreads();

    const int warp = tid >> 5, lane = tid & 31;
    const int row = blockIdx.x * 8 + warp;

    float acc[NE];
#pragma unroll
    for (int j = 0; j < NE; j++) acc[j] = 0.0f;
    const float* hr = &g_hg[(size_t)row * NHG];
#pragma unroll 4
    for (int t = 0; t < NHG / 32; t++) {
        float v = hr[t * 32 + lane];
#pragma unroll
        for (int j = 0; j < NE; j++) acc[j] = fmaf(v, sW[j][t * 32 + lane], acc[j]);
    }
#pragma unroll
    for (int j = 0; j < NE; j++)
#pragma unroll
        for (int o = 16; o > 0; o >>= 1)
            acc[j] += __shfl_xor_sync(0xffffffffu, acc[j], o);

    if (lane == 0) {
        float lg[NE];
#pragma unroll
        for (int j = 0; j < NE; j++) lg[j] = acc[j] + sb[j];
        int b0 = 0; float v0 = lg[0];
#pragma unroll
        for (int j = 1; j < NE; j++) if (lg[j] > v0) { v0 = lg[j]; b0 = j; }
        int b1 = -1; float v1 = -INFINITY;
#pragma unroll
        for (int j = 0; j < NE; j++) if (j != b0 && lg[j] > v1) { v1 = lg[j]; b1 = j; }

        float e1 = expf((v1 - v0) / TEMPR);
        float s = 1.0f + e1;
        float gg0 = 1.0f / s, gg1 = e1 / s;
#pragma unroll
        for (int j = 0; j < NE; j++) g_gates[row * NE + j] = 0.0f;
        g_gates[row * NE + b0] = gg0;
        g_gates[row * NE + b1] = gg1;

        int p0 = atomicAdd(&g_cnt[b0], 1);
        g_rowlist[b0 * NB + p0] = row;
        g_gatelist[b0 * NB + p0] = gg0;
        g_rowexp[row * 2 + 0] = b0;
        g_rowpos[row * 2 + 0] = p0;
        int p1 = atomicAdd(&g_cnt[b1], 1);
        g_rowlist[b1 * NB + p1] = row;
        g_gatelist[b1 * NB + p1] = gg1;
        g_rowexp[row * 2 + 1] = b1;
        g_rowpos[row * 2 + 1] = p1;
    }
}

// ---------------- load-balance loss ----------------
__global__ __launch_bounds__(256)
void loss_kernel()
{
    const int e = threadIdx.x >> 5, lane = threadIdx.x & 31;
    float s = 0.0f;
    for (int r = lane; r < NB; r += 32) s += g_gates[r * NE + e];
#pragma unroll
    for (int o = 16; o > 0; o >>= 1) s += __shfl_xor_sync(0xffffffffu, s, o);
    __shared__ float imp[NE];
    if (lane == 0) imp[e] = s;
    __syncthreads();
    if (threadIdx.x == 0) {
        double mi = 0.0, ml = 0.0;
        for (int j = 0; j < NE; j++) { mi += (double)imp[j]; ml += (double)g_cnt[j]; }
        mi /= NE; ml /= NE;
        double vi = 0.0, vl = 0.0;
        for (int j = 0; j < NE; j++) {
            double di = (double)imp[j] - mi;  vi += di * di;
            double dl = (double)g_cnt[j] - ml; vl += dl * dl;
        }
        vi /= (NE - 1); vl /= (NE - 1);
        g_loss = (float)((vi / (mi * mi + 1e-10) + vl / (ml * ml + 1e-10)) * 0.01);
    }
}

// ---------------- fused softmax*gate + combine + log ----------------
// warp 0: softmax slot-row of expert rowexp[0]; warp 1: rowexp[1].
// Same shuffle-reduction order and same P0+P1 combine order as before
// => bitwise-identical output.
__global__ __launch_bounds__(64)
void finalize_fused(float* __restrict__ out, int out_size)
{
    const int row = blockIdx.x;
    const int warp = threadIdx.x >> 5, lane = threadIdx.x & 31;

    __shared__ float sP[2][NC];

    const int e    = g_rowexp[row * 2 + warp];
    const int slot = g_off[e] + g_rowpos[row * 2 + warp];
    const float gt = g_gates[row * NE + e];
    const float* P = &g_P[(size_t)slot * NC];

    float v[NC / 32];
    float mx = -INFINITY;
#pragma unroll
    for (int t = 0; t < NC / 32; t++) { v[t] = P[t * 32 + lane]; mx = fmaxf(mx, v[t]); }
#pragma unroll
    for (int o = 16; o > 0; o >>= 1) mx = fmaxf(mx, __shfl_xor_sync(0xffffffffu, mx, o));
    float sum = 0.0f;
#pragma unroll
    for (int t = 0; t < NC / 32; t++) { v[t] = expf(v[t] - mx); sum += v[t]; }
#pragma unroll
    for (int o = 16; o > 0; o >>= 1) sum += __shfl_xor_sync(0xffffffffu, sum, o);
    const float inv = gt / sum;
#pragma unroll
    for (int t = 0; t < NC / 32; t++) sP[warp][t * 32 + lane] = v[t] * inv;

    __syncthreads();

    for (int c = threadIdx.x; c < NC; c += 64) {
        float comb = sP[0][c] + sP[1][c];
        if (comb == 0.0f) comb = 2.2204460492503131e-16f;
        out[(size_t)row * NC + c] = logf(comb);
    }
    if (row == 0 && threadIdx.x == 0 && out_size > NB * NC)
        out[NB * NC] = g_loss;
}

// ---------------- launch ----------------
extern "C" void kernel_launch(void* const* d_in, const int* in_sizes, int n_in,
                              void* d_out, int out_size)
{
    const float* x   = (const float*)d_in[0];
    const float* x2  = (const float*)d_in[1];
    const float* Wg1 = (const float*)d_in[2];
    const float* bg1 = (const float*)d_in[3];
    const float* Wg2 = (const float*)d_in[4];
    const float* bg2 = (const float*)d_in[5];
    const float* W1  = (const float*)d_in[6];
    const float* b1  = (const float*)d_in[7];
    const float* W2  = (const float*)d_in[8];
    const float* b2  = (const float*)d_in[9];
    float* out = (float*)d_out;

    zero_counts<<<1, 32>>>();
    gemm0_split<<<dim3(NHG / 128, NB / 128), 256>>>(x, Wg1, bg1);
    gating_topk<<<NB / 8, 256>>>(Wg2, bg2);
    offsets_kernel<<<1, 32>>>();
    emma<1><<<dim3(NH / 128, NB / 128, NE), 256>>>(x2, W1, b1);
    emma<2><<<dim3(NC / 128, NB / 128, NE), 256>>>(nullptr, W2, b2);
    loss_kernel<<<1, 256>>>();
    finalize_fused<<<NB, 64>>>(out, out_size);
}

// round 16
// speedup vs baseline: 1.0759x; 1.0759x over previous
#include <cuda_runtime.h>
#include <cuda_fp16.h>
#include <math.h>
#include <stdint.h>

// ---------------- problem constants ----------------
#define NB    4096
#define NDG   1024
#define NDI   1024
#define NHG   512
#define NE    8
#define NH    2048
#define NC    512
#define TEMPR 5.0f
#define NASSIGN (NB*2)

// ---------------- scratch ----------------
__device__ float  g_hg[NB * NHG];
__device__ float  g_gates[NB * NE];
__device__ int    g_cnt[NE];
__device__ int    g_off[NE];
__device__ int    g_rowlist[NE * NB];
__device__ float  g_gatelist[NE * NB];
__device__ int    g_rowexp[NB * 2];
__device__ int    g_rowpos[NB * 2];
__device__ __half g_He[(size_t)NASSIGN * NH];
__device__ float  g_P[(size_t)NASSIGN * NC];
__device__ float  g_loss;

__global__ void zero_counts() {
    if (threadIdx.x < NE) g_cnt[threadIdx.x] = 0;
}
__global__ void offsets_kernel() {
    if (threadIdx.x == 0) {
        int o = 0;
        for (int e = 0; e < NE; e++) { g_off[e] = o; o += g_cnt[e]; }
    }
}

// ---------------- helpers ----------------
__device__ __forceinline__ uint32_t smem_u32(const void* p) {
    uint32_t a;
    asm("{ .reg .u64 t; cvta.to.shared.u64 t, %1; cvt.u32.u64 %0, t; }" : "=r"(a) : "l"(p));
    return a;
}
__device__ __forceinline__ uint32_t packh(float a, float b) {
    __half2 h = __floats2half2_rn(a, b);
    return *reinterpret_cast<uint32_t*>(&h);
}
__device__ __forceinline__ void mma_fp16(float* d, const uint32_t* a,
                                         const uint32_t* b, const float* c) {
    asm volatile(
        "mma.sync.aligned.m16n8k16.row.col.f32.f16.f16.f32 "
        "{%0,%1,%2,%3}, {%4,%5,%6,%7}, {%8,%9}, {%10,%11,%12,%13};\n"
        : "=f"(d[0]), "=f"(d[1]), "=f"(d[2]), "=f"(d[3])
        : "r"(a[0]), "r"(a[1]), "r"(a[2]), "r"(a[3]),
          "r"(b[0]), "r"(b[1]),
          "f"(c[0]), "f"(c[1]), "f"(c[2]), "f"(c[3]));
}
__device__ __forceinline__ void ldsm_x4(uint32_t* d, uint32_t saddr) {
    asm volatile("ldmatrix.sync.aligned.m8n8.x4.shared.b16 {%0,%1,%2,%3}, [%4];"
        : "=r"(d[0]), "=r"(d[1]), "=r"(d[2]), "=r"(d[3]) : "r"(saddr));
}

// ============================================================================
// Expert GEMMs — EXACT R8/R14 source (proven local optimum).
// MODE 1: He = relu(gather(x2) @ W1[e] + b1[e])   M=cnt_e N=2048 K=1024
// MODE 2: P  = He @ W2[e] + b2[e]                 M=cnt_e N=512  K=2048
// ============================================================================
template<int MODE>
__global__ __launch_bounds__(256, 2)
void emma(const float* __restrict__ Af,
          const float* __restrict__ Wall,
          const float* __restrict__ biasAll)
{
    constexpr int BM = 128, BK = 32;
    constexpr int LDA = 20, LDB = 136;

    const int e = blockIdx.z;
    const int M = g_cnt[e];
    const int m0 = blockIdx.y * BM;
    if (m0 >= M) return;
    const int n0 = blockIdx.x * 128;

    constexpr int Kd  = (MODE == 1) ? NDI : NH;
    constexpr int ldw = (MODE == 1) ? NH  : NC;
    const float* W    = Wall + (size_t)e * Kd * ldw;
    const float* bias = biasAll + e * ldw;
    const int* rowlist = g_rowlist + e * NB;
    const size_t offE = (size_t)g_off[e];
    const __half* Ab = g_He + offE * NH;

    __shared__ uint32_t As[2][BM][LDA];
    __shared__ uint32_t Bs[2][16][LDB];

    const int tid = threadIdx.x;
    int arow[2], akc[2];
    size_t aoff[2];
#pragma unroll
    for (int c = 0; c < 2; c++) {
        int q = tid + 256 * c;
        arow[c] = q >> 2;
        akc[c]  = (q & 3) * 8;
        int gm = m0 + arow[c];
        if (MODE == 1) {
            int r = (gm < M) ? rowlist[gm] : rowlist[0];
            aoff[c] = (size_t)r * NDI;
        } else {
            int r = (gm < M) ? gm : 0;
            aoff[c] = (size_t)r * NH;
        }
    }
    int bkp[2], bnq[2];
#pragma unroll
    for (int c = 0; c < 2; c++) {
        int q = tid + 256 * c;
        bkp[c] = q >> 5;
        bnq[c] = (q & 31) * 4;
    }

    const int warp = tid >> 5;
    const int wm = warp >> 1, wn = warp & 1;
    const int lane = tid & 31;
    const int g = lane >> 2, tg = lane & 3;

    const uint32_t asbase = smem_u32(&As[0][0][0]);
    const int lr = lane & 15;
    const int lc = (lane >> 2) & 4;

    float acc[2][8][4];
#pragma unroll
    for (int i = 0; i < 2; i++)
#pragma unroll
        for (int j = 0; j < 8; j++)
#pragma unroll
            for (int q = 0; q < 4; q++) acc[i][j][q] = 0.0f;

    float4 ra[2][2];
    uint4  rab[2];
    float4 rb[2][2];

    auto LDGt = [&](int k0) {
#pragma unroll
        for (int c = 0; c < 2; c++) {
            if (MODE == 1) {
                ra[c][0] = *(const float4*)(Af + aoff[c] + k0 + akc[c]);
                ra[c][1] = *(const float4*)(Af + aoff[c] + k0 + akc[c] + 4);
            } else {
                rab[c] = *(const uint4*)(Ab + aoff[c] + k0 + akc[c]);
            }
        }
#pragma unroll
        for (int c = 0; c < 2; c++) {
            rb[c][0] = *(const float4*)(W + (size_t)(k0 + 2 * bkp[c]) * ldw + n0 + bnq[c]);
            rb[c][1] = *(const float4*)(W + (size_t)(k0 + 2 * bkp[c] + 1) * ldw + n0 + bnq[c]);
        }
    };
    auto STSt = [&](int s) {
#pragma unroll
        for (int c = 0; c < 2; c++) {
            if (MODE == 1) {
                uint4 u;
                u.x = packh(ra[c][0].x, ra[c][0].y);
                u.y = packh(ra[c][0].z, ra[c][0].w);
                u.z = packh(ra[c][1].x, ra[c][1].y);
                u.w = packh(ra[c][1].z, ra[c][1].w);
                *(uint4*)&As[s][arow[c]][akc[c] >> 1] = u;
            } else {
                *(uint4*)&As[s][arow[c]][akc[c] >> 1] = rab[c];
            }
        }
#pragma unroll
        for (int c = 0; c < 2; c++) {
            uint4 u;
            u.x = packh(rb[c][0].x, rb[c][1].x);
            u.y = packh(rb[c][0].y, rb[c][1].y);
            u.z = packh(rb[c][0].z, rb[c][1].z);
            u.w = packh(rb[c][0].w, rb[c][1].w);
            *(uint4*)&Bs[s][bkp[c]][bnq[c]] = u;
        }
    };

    LDGt(0);
    STSt(0);
    __syncthreads();

    const int T = Kd / BK;
    for (int t = 0; t < T; t++) {
        const int s = t & 1;
        if (t + 1 < T) LDGt((t + 1) * BK);

#pragma unroll
        for (int ksub = 0; ksub < 2; ksub++) {
            const int kb = ksub * 8;
            uint32_t af[2][4];
#pragma unroll
            for (int mt = 0; mt < 2; mt++) {
                const int mr = wm * 32 + mt * 16;
                const uint32_t addr = asbase +
                    ((uint32_t)(s * BM * LDA + (mr + lr) * LDA + kb + lc)) * 4u;
                ldsm_x4(af[mt], addr);
            }
#pragma unroll
            for (int nt = 0; nt < 8; nt++) {
                const int nc = wn * 64 + nt * 8 + g;
                uint32_t bf[2];
                bf[0] = Bs[s][kb + tg    ][nc];
                bf[1] = Bs[s][kb + tg + 4][nc];
#pragma unroll
                for (int mt = 0; mt < 2; mt++)
                    mma_fp16(acc[mt][nt], af[mt], bf, acc[mt][nt]);
            }
        }

        if (t + 1 < T) {
            STSt((t + 1) & 1);
            __syncthreads();
        }
    }

    __half* Ch = g_He + offE * NH;
    float*  Cf = g_P  + offE * NC;
#pragma unroll
    for (int mt = 0; mt < 2; mt++) {
        const int gm1 = m0 + wm * 32 + mt * 16 + g;
        const int gm2 = gm1 + 8;
#pragma unroll
        for (int nt = 0; nt < 8; nt++) {
            const int col = n0 + wn * 64 + nt * 8 + tg * 2;
            const float b0 = bias[col], b1 = bias[col + 1];
            if (MODE == 1) {
                if (gm1 < M) {
                    float v0 = fmaxf(acc[mt][nt][0] + b0, 0.f);
                    float v1 = fmaxf(acc[mt][nt][1] + b1, 0.f);
                    *(uint32_t*)(Ch + (size_t)gm1 * NH + col) = packh(v0, v1);
                }
                if (gm2 < M) {
                    float v0 = fmaxf(acc[mt][nt][2] + b0, 0.f);
                    float v1 = fmaxf(acc[mt][nt][3] + b1, 0.f);
                    *(uint32_t*)(Ch + (size_t)gm2 * NH + col) = packh(v0, v1);
                }
            } else {
                if (gm1 < M)
                    *(float2*)(Cf + (size_t)gm1 * NC + col) =
                        make_float2(acc[mt][nt][0] + b0, acc[mt][nt][1] + b1);
                if (gm2 < M)
                    *(float2*)(Cf + (size_t)gm2 * NC + col) =
                        make_float2(acc[mt][nt][2] + b0, acc[mt][nt][3] + b1);
            }
        }
    }
}

// ============================================================================
// Gating layer 1 — EXACT R14 source (fp16-split + register prefetch; no ldsm).
// ============================================================================
__global__ __launch_bounds__(256, 2)
void gemm0_split(const float* __restrict__ A,
                 const float* __restrict__ W,
                 const float* __restrict__ bias)
{
    constexpr int BM = 128, BK = 32;
    constexpr int LDA = 20, LDB = 136;
    constexpr int ldw = NHG;

    const int m0 = blockIdx.y * BM;
    const int n0 = blockIdx.x * 128;

    __shared__ uint32_t AsH[BM][LDA];
    __shared__ uint32_t AsL[BM][LDA];
    __shared__ uint32_t BsH[16][LDB];
    __shared__ uint32_t BsL[16][LDB];

    const int tid = threadIdx.x;
    int arow[2], akc[2];
    size_t aoff[2];
#pragma unroll
    for (int c = 0; c < 2; c++) {
        int q = tid + 256 * c;
        arow[c] = q >> 2;
        akc[c]  = (q & 3) * 8;
        aoff[c] = (size_t)(m0 + arow[c]) * NDG;
    }
    int bkp[2], bnq[2];
#pragma unroll
    for (int c = 0; c < 2; c++) {
        int q = tid + 256 * c;
        bkp[c] = q >> 5;
        bnq[c] = (q & 31) * 4;
    }

    const int warp = tid >> 5;
    const int wm = warp >> 1, wn = warp & 1;
    const int lane = tid & 31;
    const int g = lane >> 2, tg = lane & 3;

    float acc[2][8][4];
#pragma unroll
    for (int i = 0; i < 2; i++)
#pragma unroll
        for (int j = 0; j < 8; j++)
#pragma unroll
            for (int q = 0; q < 4; q++) acc[i][j][q] = 0.0f;

    auto splitpack = [](float a, float b, uint32_t& uh, uint32_t& ul) {
        __half ha = __float2half_rn(a);
        __half hb = __float2half_rn(b);
        float la = a - __half2float(ha);
        float lb = b - __half2float(hb);
        __half2 h2; h2.x = ha; h2.y = hb;
        uh = *reinterpret_cast<uint32_t*>(&h2);
        ul = packh(la, lb);
    };

    float4 ra[2][2], rb[2][2];   // persistent register staging (tile t)

    auto LDGt = [&](int k0) {
#pragma unroll
        for (int c = 0; c < 2; c++) {
            ra[c][0] = *(const float4*)(A + aoff[c] + k0 + akc[c]);
            ra[c][1] = *(const float4*)(A + aoff[c] + k0 + akc[c] + 4);
            rb[c][0] = *(const float4*)(W + (size_t)(k0 + 2 * bkp[c]) * ldw + n0 + bnq[c]);
            rb[c][1] = *(const float4*)(W + (size_t)(k0 + 2 * bkp[c] + 1) * ldw + n0 + bnq[c]);
        }
    };
    auto STSt = [&]() {
#pragma unroll
        for (int c = 0; c < 2; c++) {
            uint4 uh, ul;
            splitpack(ra[c][0].x, ra[c][0].y, uh.x, ul.x);
            splitpack(ra[c][0].z, ra[c][0].w, uh.y, ul.y);
            splitpack(ra[c][1].x, ra[c][1].y, uh.z, ul.z);
            splitpack(ra[c][1].z, ra[c][1].w, uh.w, ul.w);
            *(uint4*)&AsH[arow[c]][akc[c] >> 1] = uh;
            *(uint4*)&AsL[arow[c]][akc[c] >> 1] = ul;
        }
#pragma unroll
        for (int c = 0; c < 2; c++) {
            uint4 uh, ul;
            splitpack(rb[c][0].x, rb[c][1].x, uh.x, ul.x);
            splitpack(rb[c][0].y, rb[c][1].y, uh.y, ul.y);
            splitpack(rb[c][0].z, rb[c][1].z, uh.z, ul.z);
            splitpack(rb[c][0].w, rb[c][1].w, uh.w, ul.w);
            *(uint4*)&BsH[bkp[c]][bnq[c]] = uh;
            *(uint4*)&BsL[bkp[c]][bnq[c]] = ul;
        }
    };

    const int T = NDG / BK;
    LDGt(0);
    for (int t = 0; t < T; t++) {
        __syncthreads();
        STSt();
        __syncthreads();
        if (t + 1 < T) LDGt((t + 1) * BK);

#pragma unroll
        for (int ksub = 0; ksub < 2; ksub++) {
            const int kb = ksub * 8;
            uint32_t afh[2][4], afl[2][4];
#pragma unroll
            for (int mt = 0; mt < 2; mt++) {
                const int mr = wm * 32 + mt * 16;
                afh[mt][0] = AsH[mr + g    ][kb + tg];
                afh[mt][1] = AsH[mr + g + 8][kb + tg];
                afh[mt][2] = AsH[mr + g    ][kb + tg + 4];
                afh[mt][3] = AsH[mr + g + 8][kb + tg + 4];
                afl[mt][0] = AsL[mr + g    ][kb + tg];
                afl[mt][1] = AsL[mr + g + 8][kb + tg];
                afl[mt][2] = AsL[mr + g    ][kb + tg + 4];
                afl[mt][3] = AsL[mr + g + 8][kb + tg + 4];
            }
#pragma unroll
            for (int nt = 0; nt < 8; nt++) {
                const int nc = wn * 64 + nt * 8 + g;
                uint32_t bfh[2], bfl[2];
                bfh[0] = BsH[kb + tg    ][nc];
                bfh[1] = BsH[kb + tg + 4][nc];
                bfl[0] = BsL[kb + tg    ][nc];
                bfl[1] = BsL[kb + tg + 4][nc];
#pragma unroll
                for (int mt = 0; mt < 2; mt++) {
                    mma_fp16(acc[mt][nt], afh[mt], bfh, acc[mt][nt]);
                    mma_fp16(acc[mt][nt], afh[mt], bfl, acc[mt][nt]);
                    mma_fp16(acc[mt][nt], afl[mt], bfh, acc[mt][nt]);
                }
            }
        }
    }

#pragma unroll
    for (int mt = 0; mt < 2; mt++) {
        const int gm1 = m0 + wm * 32 + mt * 16 + g;
        const int gm2 = gm1 + 8;
#pragma unroll
        for (int nt = 0; nt < 8; nt++) {
            const int col = n0 + wn * 64 + nt * 8 + tg * 2;
            const float b0 = bias[col], b1 = bias[col + 1];
            *(float2*)(g_hg + (size_t)gm1 * NHG + col) =
                make_float2(fmaxf(acc[mt][nt][0] + b0, 0.f), fmaxf(acc[mt][nt][1] + b1, 0.f));
            *(float2*)(g_hg + (size_t)gm2 * NHG + col) =
                make_float2(fmaxf(acc[mt][nt][2] + b0, 0.f), fmaxf(acc[mt][nt][3] + b1, 0.f));
        }
    }
}

// ---------------- gating layer 2 + top-2 + dispatch (FROZEN) ----------------
__global__ __launch_bounds__(256)
void gating_topk(const float* __restrict__ Wg2, const float* __restrict__ bg2)
{
    __shared__ float sW[NE][NHG];
    __shared__ float sb[NE];
    const int tid = threadIdx.x;
    for (int i = tid; i < NE * NHG; i += 256)
        sW[i >> 9][i & (NHG - 1)] = Wg2[(i & (NHG - 1)) * NE + (i >> 9)];
    if (tid < NE) sb[tid] = bg2[tid];
    __syncthreads();

    const int warp = tid >> 5, lane = tid & 31;
    const int row = blockIdx.x * 8 + warp;

    float acc[NE];
#pragma unroll
    for (int j = 0; j < NE; j++) acc[j] = 0.0f;
    const float* hr = &g_hg[(size_t)row * NHG];
#pragma unroll 4
    for (int t = 0; t < NHG / 32; t++) {
        float v = hr[t * 32 + lane];
#pragma unroll
        for (int j = 0; j < NE; j++) acc[j] = fmaf(v, sW[j][t * 32 + lane], acc[j]);
    }
#pragma unroll
    for (int j = 0; j < NE; j++)
#pragma unroll
        for (int o = 16; o > 0; o >>= 1)
            acc[j] += __shfl_xor_sync(0xffffffffu, acc[j], o);

    if (lane == 0) {
        float lg[NE];
#pragma unroll
        for (int j = 0; j < NE; j++) lg[j] = acc[j] + sb[j];
        int b0 = 0; float v0 = lg[0];
#pragma unroll
        for (int j = 1; j < NE; j++) if (lg[j] > v0) { v0 = lg[j]; b0 = j; }
        int b1 = -1; float v1 = -INFINITY;
#pragma unroll
        for (int j = 0; j < NE; j++) if (j != b0 && lg[j] > v1) { v1 = lg[j]; b1 = j; }

        float e1 = expf((v1 - v0) / TEMPR);
        float s = 1.0f + e1;
        float gg0 = 1.0f / s, gg1 = e1 / s;
#pragma unroll
        for (int j = 0; j < NE; j++) g_gates[row * NE + j] = 0.0f;
        g_gates[row * NE + b0] = gg0;
        g_gates[row * NE + b1] = gg1;

        int p0 = atomicAdd(&g_cnt[b0], 1);
        g_rowlist[b0 * NB + p0] = row;
        g_gatelist[b0 * NB + p0] = gg0;
        g_rowexp[row * 2 + 0] = b0;
        g_rowpos[row * 2 + 0] = p0;
        int p1 = atomicAdd(&g_cnt[b1], 1);
        g_rowlist[b1 * NB + p1] = row;
        g_gatelist[b1 * NB + p1] = gg1;
        g_rowexp[row * 2 + 1] = b1;
        g_rowpos[row * 2 + 1] = p1;
    }
}

// ---------------- load-balance loss ----------------
__global__ __launch_bounds__(256)
void loss_kernel()
{
    const int e = threadIdx.x >> 5, lane = threadIdx.x & 31;
    float s = 0.0f;
    for (int r = lane; r < NB; r += 32) s += g_gates[r * NE + e];
#pragma unroll
    for (int o = 16; o > 0; o >>= 1) s += __shfl_xor_sync(0xffffffffu, s, o);
    __shared__ float imp[NE];
    if (lane == 0) imp[e] = s;
    __syncthreads();
    if (threadIdx.x == 0) {
        double mi = 0.0, ml = 0.0;
        for (int j = 0; j < NE; j++) { mi += (double)imp[j]; ml += (double)g_cnt[j]; }
        mi /= NE; ml /= NE;
        double vi = 0.0, vl = 0.0;
        for (int j = 0; j < NE; j++) {
            double di = (double)imp[j] - mi;  vi += di * di;
            double dl = (double)g_cnt[j] - ml; vl += dl * dl;
        }
        vi /= (NE - 1); vl /= (NE - 1);
        g_loss = (float)((vi / (mi * mi + 1e-10) + vl / (ml * ml + 1e-10)) * 0.01);
    }
}

// ---------------- fused softmax*gate + combine + log ----------------
// warp 0: softmax slot-row of expert rowexp[0]; warp 1: rowexp[1].
// Same shuffle-reduction order and same P0+P1 combine order as the unfused
// pair => bitwise-identical output.
__global__ __launch_bounds__(64)
void finalize_fused(float* __restrict__ out, int out_size)
{
    const int row = blockIdx.x;
    const int warp = threadIdx.x >> 5, lane = threadIdx.x & 31;

    __shared__ float sP[2][NC];

    const int e    = g_rowexp[row * 2 + warp];
    const int slot = g_off[e] + g_rowpos[row * 2 + warp];
    const float gt = g_gates[row * NE + e];
    const float* P = &g_P[(size_t)slot * NC];

    float v[NC / 32];
    float mx = -INFINITY;
#pragma unroll
    for (int t = 0; t < NC / 32; t++) { v[t] = P[t * 32 + lane]; mx = fmaxf(mx, v[t]); }
#pragma unroll
    for (int o = 16; o > 0; o >>= 1) mx = fmaxf(mx, __shfl_xor_sync(0xffffffffu, mx, o));
    float sum = 0.0f;
#pragma unroll
    for (int t = 0; t < NC / 32; t++) { v[t] = expf(v[t] - mx); sum += v[t]; }
#pragma unroll
    for (int o = 16; o > 0; o >>= 1) sum += __shfl_xor_sync(0xffffffffu, sum, o);
    const float inv = gt / sum;
#pragma unroll
    for (int t = 0; t < NC / 32; t++) sP[warp][t * 32 + lane] = v[t] * inv;

    __syncthreads();

    for (int c = threadIdx.x; c < NC; c += 64) {
        float comb = sP[0][c] + sP[1][c];
        if (comb == 0.0f) comb = 2.2204460492503131e-16f;
        out[(size_t)row * NC + c] = logf(comb);
    }
    if (row == 0 && threadIdx.x == 0 && out_size > NB * NC)
        out[NB * NC] = g_loss;
}

// ---------------- launch ----------------
extern "C" void kernel_launch(void* const* d_in, const int* in_sizes, int n_in,
                              void* d_out, int out_size)
{
    const float* x   = (const float*)d_in[0];
    const float* x2  = (const float*)d_in[1];
    const float* Wg1 = (const float*)d_in[2];
    const float* bg1 = (const float*)d_in[3];
    const float* Wg2 = (const float*)d_in[4];
    const float* bg2 = (const float*)d_in[5];
    const float* W1  = (const float*)d_in[6];
    const float* b1  = (const float*)d_in[7];
    const float* W2  = (const float*)d_in[8];
    const float* b2  = (const float*)d_in[9];
    float* out = (float*)d_out;

    zero_counts<<<1, 32>>>();
    gemm0_split<<<dim3(NHG / 128, NB / 128), 256>>>(x, Wg1, bg1);
    gating_topk<<<NB / 8, 256>>>(Wg2, bg2);
    offsets_kernel<<<1, 32>>>();
    emma<1><<<dim3(NH / 128, NB / 128, NE), 256>>>(x2, W1, b1);
    emma<2><<<dim3(NC / 128, NB / 128, NE), 256>>>(nullptr, W2, b2);
    loss_kernel<<<1, 256>>>();
    finalize_fused<<<NB, 64>>>(out, out_size);
}